// round 9
// baseline (speedup 1.0000x reference)
#include <cuda_runtime.h>
#include <cstdint>

// Shapes: x[8,64,512,512] f32, W[64,64], b[64], seg_w[4,4] -> out[8,64,512,512]
// SEG=4 -> 128x128 blocks. A "band" = one (b,c,i) slab of 128 rows = 16384 float4.
// 2048 bands; 1024 CTAs x 2 bands = perfectly uniform, single resident wave.
#define Bb 8
#define Cc 64
#define Oo 64
#define BAND_F4 16384
#define GRID    1024

// scratch (__device__ globals: allocation-free rule)
__device__ float g_pooled[Bb*Cc*16];     // [b][c][i*4+j], mean-scaled
__device__ unsigned g_count = 0;          // barrier arrival count (self-resetting)
__device__ unsigned g_gen   = 0;          // barrier generation (monotonic)

// ---------------------------------------------------------------------------
// Fused kernel: phase 1 pool -> grid barrier -> phase 2 linear+broadcast.
// Phases stay PURE (all-read then all-write): mixed R/W traffic measured
// ~4.4-5 TB/s aggregate vs 6.9/6.2 TB/s for pure phases. The in-kernel
// barrier removes the ~17us inter-kernel launch gap.
// ---------------------------------------------------------------------------
__global__ void __launch_bounds__(256, 8) fused_kernel(
    const float4* __restrict__ x,
    const float*  __restrict__ Wm,
    const float*  __restrict__ bias,
    const float*  __restrict__ segw,
    float4* __restrict__ out)
{
    const int tid  = threadIdx.x;
    const int warp = tid >> 5;
    const int j    = (tid & 127) >> 5;            // fixed column segment

    __shared__ float ws[8];

    // ================= Phase 1: segment mean pool (read 512 MiB) ==========
    #pragma unroll
    for (int sub = 0; sub < 2; sub++) {
        const int g = blockIdx.x * 2 + sub;       // band 0..2047
        const float4* base = x + (size_t)g * BAND_F4;

        float acc = 0.0f;
        #pragma unroll 8
        for (int idx = tid; idx < BAND_F4; idx += 256) {
            float4 v = base[idx];
            acc += (v.x + v.y) + (v.z + v.w);
        }
        #pragma unroll
        for (int off = 16; off; off >>= 1)
            acc += __shfl_xor_sync(0xffffffffu, acc, off);
        if ((tid & 31) == 0) ws[warp] = acc;      // warp w covers j = w&3
        __syncthreads();

        if (tid < 4) {
            const float inv = 1.0f / 16384.0f;
            g_pooled[(g >> 2) * 16 + (g & 3) * 4 + tid] =
                (ws[tid] + ws[tid + 4]) * inv;
        }
        __syncthreads();                          // ws reuse safe
    }

    // ================= Grid barrier (sense-reversing, replay-safe) ========
    if (tid == 0) {
        __threadfence();                          // release g_pooled writes
        unsigned gen = *(volatile unsigned*)&g_gen;
        unsigned old = atomicAdd(&g_count, 1u);
        if (old == GRID - 1u) {
            g_count = 0u;                         // reset for next replay
            __threadfence();
            atomicAdd(&g_gen, 1u);                // release everyone
        } else {
            while (*(volatile unsigned*)&g_gen == gen) __nanosleep(64);
        }
        __threadfence();                          // acquire
    }
    __syncthreads();

    // ================= Phase 2: linear + broadcast (write 512 MiB) ========
    #pragma unroll
    for (int sub = 0; sub < 2; sub++) {
        const int g  = blockIdx.x * 2 + sub;      // band 0..2047
        const int bo = g >> 2;                    // b*O + o
        const int i  = g & 3;
        const int b  = bo >> 6;
        const int o  = bo & (Oo - 1);
        const int ij = i * 4 + j;

        const float* p  = g_pooled + (b * Cc) * 16 + ij;
        const float* wr = Wm + o * Cc;
        float a = bias[o];
        #pragma unroll 8
        for (int c = 0; c < Cc; c++)
            a = fmaf(p[c * 16], wr[c], a);
        const float v = a * segw[ij];
        const float4 f = make_float4(v, v, v, v);

        float4* base = out + (size_t)g * BAND_F4;
        #pragma unroll 8
        for (int idx = tid; idx < BAND_F4; idx += 256)
            base[idx] = f;
    }
}

// ---------------------------------------------------------------------------
extern "C" void kernel_launch(void* const* d_in, const int* in_sizes, int n_in,
                              void* d_out, int out_size)
{
    const float4* x    = (const float4*)d_in[0];
    const float*  Wm   = (const float*)d_in[1];
    const float*  bias = (const float*)d_in[2];
    const float*  segw = (const float*)d_in[3];
    float4* out = (float4*)d_out;

    fused_kernel<<<GRID, 256>>>(x, Wm, bias, segw, out);
}

// round 10
// speedup vs baseline: 1.0286x; 1.0286x over previous
#include <cuda_runtime.h>
#include <cstdint>

// Shapes: x[8,64,512,512] f32, W[64,64], b[64], seg_w[4,4] -> out[8,64,512,512]
// SEG=4 -> 128x128 blocks. A "band" = one (b,c,i) slab of 128 rows = 16384 float4.
// 2048 bands. Persistent grid of 1184 CTAs (8/SM * 148 SMs = one resident wave)
// pulls bands from a dynamic ticket -> perfect SM load balance, no ragged waves.
#define Bb 8
#define Cc 64
#define Oo 64
#define BAND_F4 16384
#define NBAND   2048
#define GRID    1184

// scratch (__device__ globals: allocation-free rule)
__device__ float    g_pooled[Bb*Cc*16];  // [b][c][i*4+j], mean-scaled
__device__ unsigned g_pool_tkt  = 0;     // reset by bcast_kernel for next replay
__device__ unsigned g_bcast_tkt = 0;     // reset by pool_kernel for next replay

// ---------------------------------------------------------------------------
// Kernel 1: segment mean pool (pure-read phase). Dynamic ticket over bands.
// Per band: fixed column segment per thread, float4 stream accumulate,
// warp-shuffle reduce, 8-warp combine -> 4 means stored to g_pooled.
// ---------------------------------------------------------------------------
__global__ void __launch_bounds__(256, 8) pool_kernel(const float4* __restrict__ x)
{
    // reset the *other* kernel's ticket (bcast is quiescent: kernels serialize)
    if (blockIdx.x == 0 && threadIdx.x == 0) g_bcast_tkt = 0u;

    const int tid  = threadIdx.x;
    const int warp = tid >> 5;

    __shared__ float    ws[8];
    __shared__ unsigned s_pos;

    for (;;) {
        if (tid == 0) s_pos = atomicAdd(&g_pool_tkt, 1u);
        __syncthreads();
        const unsigned g = s_pos;                  // band index
        if (g >= NBAND) return;

        const float4* base = x + (size_t)g * BAND_F4;

        float acc = 0.0f;
        #pragma unroll 8
        for (int idx = tid; idx < BAND_F4; idx += 256) {
            float4 v = base[idx];
            acc += (v.x + v.y) + (v.z + v.w);
        }
        #pragma unroll
        for (int off = 16; off; off >>= 1)
            acc += __shfl_xor_sync(0xffffffffu, acc, off);
        if ((tid & 31) == 0) ws[warp] = acc;       // warp w covers j = w&3
        __syncthreads();

        if (tid < 4) {
            const float inv = 1.0f / 16384.0f;
            // band g -> bc = g>>2, i = g&3 ; cell = bc*16 + i*4 + j
            g_pooled[(g >> 2) * 16 + (g & 3) * 4 + tid] =
                (ws[tid] + ws[tid + 4]) * inv;
        }
        __syncthreads();                           // ws + s_pos safe for next iter
    }
}

// ---------------------------------------------------------------------------
// Kernel 2: inlined linear + broadcast (pure-write phase). Dynamic ticket.
// Per band: each thread computes the 64-channel dot for its (b,o,i,j) cell
// (warp-uniform addresses -> broadcast loads, L1-hot), then streams constant
// float4 stores over its column-segment slice.
// ---------------------------------------------------------------------------
__global__ void __launch_bounds__(256, 8) bcast_kernel(
    const float* __restrict__ Wm,
    const float* __restrict__ bias,
    const float* __restrict__ segw,
    float4* __restrict__ out)
{
    // reset pool's ticket for the next graph replay (pool is quiescent now)
    if (blockIdx.x == 0 && threadIdx.x == 0) g_pool_tkt = 0u;

    const int tid = threadIdx.x;
    const int j   = (tid & 127) >> 5;              // fixed column segment

    __shared__ unsigned s_pos;

    for (;;) {
        if (tid == 0) s_pos = atomicAdd(&g_bcast_tkt, 1u);
        __syncthreads();
        const unsigned g = s_pos;                  // band index
        if (g >= NBAND) return;

        const int bo = g >> 2;                     // b*O + o
        const int i  = g & 3;
        const int b  = bo >> 6;
        const int o  = bo & (Oo - 1);
        const int ij = i * 4 + j;

        const float* p  = g_pooled + (b * Cc) * 16 + ij;
        const float* wr = Wm + o * Cc;
        float a = bias[o];
        #pragma unroll 8
        for (int c = 0; c < Cc; c++)
            a = fmaf(p[c * 16], wr[c], a);
        const float v = a * segw[ij];
        const float4 f = make_float4(v, v, v, v);

        float4* base = out + (size_t)g * BAND_F4;
        #pragma unroll 8
        for (int idx = tid; idx < BAND_F4; idx += 256)
            base[idx] = f;

        __syncthreads();                           // s_pos safe for next iter
    }
}

// ---------------------------------------------------------------------------
extern "C" void kernel_launch(void* const* d_in, const int* in_sizes, int n_in,
                              void* d_out, int out_size)
{
    const float4* x    = (const float4*)d_in[0];
    const float*  Wm   = (const float*)d_in[1];
    const float*  bias = (const float*)d_in[2];
    const float*  segw = (const float*)d_in[3];
    float4* out = (float4*)d_out;

    pool_kernel<<<GRID, 256>>>(x);
    bcast_kernel<<<GRID, 256>>>(Wm, bias, segw, out);
}

// round 11
// speedup vs baseline: 1.0345x; 1.0057x over previous
#include <cuda_runtime.h>
#include <cstdint>

// Shapes: x[8,64,512,512] f32, W[64,64], b[64], seg_w[4,4] -> out[8,64,512,512]
// SEG=4 -> 128x128 blocks. A "band" = one (b,c,i) slab of 128 rows = 16384 float4.
// 2048 bands total.
//
// Component-wise best (measured):
//  - pool: static 2048 CTAs, one band each (77.9us @ 6.94 TB/s) -- reads like
//    oversubscribed static waves; per-band barriers/tickets cost ~12us.
//  - bcast: persistent 1184-CTA ticket loop (84.7us) -- writes like one
//    resident wave with dynamic balance; static 2048 costs ~7-9us more.
#define Bb 8
#define Cc 64
#define Oo 64
#define BAND_F4 16384
#define NBAND   2048
#define BGRID   1184            // 8 CTAs/SM * 148 SMs, one resident wave

// scratch (__device__ globals: allocation-free rule)
__device__ float    g_pooled[Bb*Cc*16];  // [b][c][i*4+j], mean-scaled
__device__ unsigned g_bcast_tkt = 0;     // reset by pool_kernel each replay

// ---------------------------------------------------------------------------
// Kernel 1: segment mean pool. One CTA per band (b,c,i). Each thread has a
// fixed column segment j=(tid&127)>>5; float4 stream accumulate, warp-shuffle
// reduce, 8-warp combine -> 4 means.
// ---------------------------------------------------------------------------
__global__ __launch_bounds__(256) void pool_kernel(const float4* __restrict__ x)
{
    // reset bcast ticket for this replay (bcast kernel is quiescent: serialized)
    if (blockIdx.x == 0 && threadIdx.x == 0) g_bcast_tkt = 0u;

    const int g = blockIdx.x;                    // band index 0..2047
    const float4* base = x + (size_t)g * BAND_F4;

    float acc = 0.0f;
    #pragma unroll 8
    for (int idx = threadIdx.x; idx < BAND_F4; idx += 256) {
        float4 v = base[idx];
        acc += (v.x + v.y) + (v.z + v.w);
    }

    #pragma unroll
    for (int off = 16; off; off >>= 1)
        acc += __shfl_xor_sync(0xffffffffu, acc, off);

    __shared__ float ws[8];
    const int warp = threadIdx.x >> 5;
    if ((threadIdx.x & 31) == 0) ws[warp] = acc;  // warp w covers j = w&3
    __syncthreads();

    if (threadIdx.x < 4) {
        const float inv = 1.0f / 16384.0f;
        // band g -> bc = g>>2, i = g&3 ; cell = bc*16 + i*4 + j
        g_pooled[(g >> 2) * 16 + (g & 3) * 4 + threadIdx.x] =
            (ws[threadIdx.x] + ws[threadIdx.x + 4]) * inv;
    }
}

// ---------------------------------------------------------------------------
// Kernel 2: inlined linear + broadcast. Persistent ticket loop over bands.
// Per band: each thread computes the 64-channel dot for its (b,o,i,j) cell
// (warp-uniform addresses -> broadcast loads, L1-hot), then streams constant
// float4 stores over its column-segment slice.
// ---------------------------------------------------------------------------
__global__ void __launch_bounds__(256, 8) bcast_kernel(
    const float* __restrict__ Wm,
    const float* __restrict__ bias,
    const float* __restrict__ segw,
    float4* __restrict__ out)
{
    const int tid = threadIdx.x;
    const int j   = (tid & 127) >> 5;            // fixed column segment

    __shared__ unsigned s_pos;

    for (;;) {
        if (tid == 0) s_pos = atomicAdd(&g_bcast_tkt, 1u);
        __syncthreads();
        const unsigned g = s_pos;                // band index
        if (g >= NBAND) return;

        const int bo = g >> 2;                   // b*O + o
        const int i  = g & 3;
        const int b  = bo >> 6;
        const int o  = bo & (Oo - 1);
        const int ij = i * 4 + j;

        const float* p  = g_pooled + (b * Cc) * 16 + ij;
        const float* wr = Wm + o * Cc;
        float a = bias[o];
        #pragma unroll 8
        for (int c = 0; c < Cc; c++)
            a = fmaf(p[c * 16], wr[c], a);
        const float v = a * segw[ij];
        const float4 f = make_float4(v, v, v, v);

        float4* base = out + (size_t)g * BAND_F4;
        #pragma unroll 8
        for (int idx = tid; idx < BAND_F4; idx += 256)
            base[idx] = f;

        __syncthreads();                         // s_pos safe for next iter
    }
}

// ---------------------------------------------------------------------------
extern "C" void kernel_launch(void* const* d_in, const int* in_sizes, int n_in,
                              void* d_out, int out_size)
{
    const float4* x    = (const float4*)d_in[0];
    const float*  Wm   = (const float*)d_in[1];
    const float*  bias = (const float*)d_in[2];
    const float*  segw = (const float*)d_in[3];
    float4* out = (float4*)d_out;

    pool_kernel<<<NBAND, 256>>>(x);
    bcast_kernel<<<BGRID, 256>>>(Wm, bias, segw, out);
}